// round 8
// baseline (speedup 1.0000x reference)
#include <cuda_runtime.h>
#include <cstdint>
#include <cstddef>

// ---------------------------------------------------------------------------
// Bidirectional LSTM. 512 seqs (256 batch x 2 dirs), 4 per CTA, 128 CTAs.
//
// Round 8: cross-sequence pipelining.
//   Producers (warps 8-15, 256 thr): thread = 2 gate rows x (32-h + 16-enc)
//     k-half, weights in regs. Per step, sweep seqs 0..3 in sub-slots:
//     sync empty_s -> gates-partial(s,t) = [bias +] Wh.h + Wih.enc -> STS
//     -> arrive full_s. While seq s's epilogue runs, producers compute s+1..
//   Service group per seq (64 thr): sync full_s -> epilogue (1 cell/thr) ->
//     STS h -> arrive empty_s -> x loader + stage1 enc(t+2) (smem weights).
//   Named bars: empty_s = 1+s, full_s = 5+s, count 320 (256 prod + 64 svc).
// ---------------------------------------------------------------------------

#define T_STEPS 4096
#define HID     64
#define KIN     60
#define ENC     32

__device__ float g_cfin[2][256][HID];

typedef unsigned long long ull;

__device__ __forceinline__ ull pack2(float lo, float hi) {
    ull u;
    asm("mov.b64 %0, {%1, %2};" : "=l"(u) : "f"(lo), "f"(hi));
    return u;
}
__device__ __forceinline__ void unpack2(ull u, float& lo, float& hi) {
    asm("mov.b64 {%0, %1}, %2;" : "=f"(lo), "=f"(hi) : "l"(u));
}
__device__ __forceinline__ void ffma2(ull& d, ull a, ull b) {
    asm("fma.rn.f32x2 %0, %1, %2, %0;" : "+l"(d) : "l"(a), "l"(b));
}
__device__ __forceinline__ float fast_sigmoid(float x) {
    return __fdividef(1.0f, 1.0f + __expf(-x));
}
__device__ __forceinline__ float fast_tanh(float x) {
    return 1.0f - __fdividef(2.0f, __expf(2.0f * x) + 1.0f);
}

#define BSYNC(id, cnt) asm volatile("bar.sync %0, %1;"   :: "r"(id), "r"(cnt) : "memory")
#define BARRV(id, cnt) asm volatile("bar.arrive %0, %1;" :: "r"(id), "r"(cnt) : "memory")

__global__ void pad_kernel() {}

// ---------------------------------------------------------------------------
__global__ void __launch_bounds__(512, 1)
lstm_kernel(const float* __restrict__ cin,
            const float* __restrict__ W_enc,  const float* __restrict__ b_enc,
            const float* __restrict__ W_ih_f, const float* __restrict__ W_hh_f,
            const float* __restrict__ b_f,
            const float* __restrict__ W_ih_b, const float* __restrict__ W_hh_b,
            const float* __restrict__ b_b) {
    const int dir = blockIdx.x >> 6;
    const int bg  = blockIdx.x & 63;
    const int tid = threadIdx.x;

    __shared__ __align__(16) float  hbuf[4][HID];        // h_t per seq
    __shared__ __align__(16) float  xr[4][3][KIN];       // raw x ring per seq
    __shared__ __align__(16) float  encr[4][3][ENC];     // encoded x ring per seq
    __shared__ __align__(8)  float  gps[4][2][256];      // gate partials [seq][kh]
    __shared__ __align__(8)  float2 wesmT[30][ENC];      // W_enc transposed pairs

    const float* W_ih = dir ? W_ih_b : W_ih_f;
    const float* W_hh = dir ? W_hh_b : W_hh_f;
    const float* bv   = dir ? b_b    : b_f;

#define TMAP(t) (dir ? (T_STEPS - 1 - (t)) : (t))

    const bool is_prod = (tid >= 256);

    // wesmT fill (all threads): wesmT[i][r] = (W_enc[r][2i], W_enc[r][2i+1])
    for (int idx = tid; idx < 30 * ENC; idx += 512) {
        const int i = idx >> 5, r = idx & 31;
        wesmT[i][r] = make_float2(W_enc[r * KIN + 2 * i], W_enc[r * KIN + 2 * i + 1]);
    }

    if (is_prod) {
        // ---------------- producer: warps 8-15 ----------------
        const int p  = tid - 256;
        const int kh = p >> 7;            // k-half (h: 32 dims, enc: 16 dims)
        const int pr = p & 127;
        const int r0 = 2 * pr;            // 2 gate rows

        ull whA[16], whB[16], wiA[8], wiB[8];
        {
            const float* a = W_hh + (size_t)r0 * HID + kh * 32;
            const float* b = a + HID;
#pragma unroll
            for (int i = 0; i < 16; i++) {
                float2 x = *reinterpret_cast<const float2*>(a + 2 * i);
                float2 y = *reinterpret_cast<const float2*>(b + 2 * i);
                whA[i] = pack2(x.x, x.y);
                whB[i] = pack2(y.x, y.y);
            }
            const float* c2 = W_ih + (size_t)r0 * ENC + kh * 16;
            const float* d2 = c2 + ENC;
#pragma unroll
            for (int i = 0; i < 8; i++) {
                float2 x = *reinterpret_cast<const float2*>(c2 + 2 * i);
                float2 y = *reinterpret_cast<const float2*>(d2 + 2 * i);
                wiA[i] = pack2(x.x, x.y);
                wiB[i] = pack2(y.x, y.y);
            }
        }
        const ull initA = (kh == 0) ? pack2(bv[r0], 0.0f)     : 0ull;
        const ull initB = (kh == 0) ? pack2(bv[r0 + 1], 0.0f) : 0ull;

        __syncthreads();   // wesmT + service prologue setup

        int m3 = 0;        // t % 3
        for (int t = 0; t < T_STEPS; t++) {
#pragma unroll
            for (int s = 0; s < 4; s++) {
                BSYNC(1 + s, 320);    // empty_s: h(s,t) + enc(s,t) consumable
                ull aA = initA, aB = initB;
                const float* hb = &hbuf[s][kh * 32];
                const float* eb = &encr[s][m3][kh * 16];
#pragma unroll
                for (int c = 0; c < 8; c++) {
                    const ulonglong2 v = *reinterpret_cast<const ulonglong2*>(hb + 4 * c);
                    ffma2(aA, whA[2 * c], v.x); ffma2(aA, whA[2 * c + 1], v.y);
                    ffma2(aB, whB[2 * c], v.x); ffma2(aB, whB[2 * c + 1], v.y);
                }
#pragma unroll
                for (int c = 0; c < 4; c++) {
                    const ulonglong2 v = *reinterpret_cast<const ulonglong2*>(eb + 4 * c);
                    ffma2(aA, wiA[2 * c], v.x); ffma2(aA, wiA[2 * c + 1], v.y);
                    ffma2(aB, wiB[2 * c], v.x); ffma2(aB, wiB[2 * c + 1], v.y);
                }
                float lA, hA, lB, hB;
                unpack2(aA, lA, hA);
                unpack2(aB, lB, hB);
                *reinterpret_cast<float2*>(&gps[s][kh][r0]) = make_float2(lA + hA, lB + hB);
                BARRV(5 + s, 320);    // full_s: partials(s,t) published
            }
            m3 = (m3 == 2) ? 0 : m3 + 1;
        }
    } else {
        // ---------------- service: one 64-thread group per seq ----------------
        const int s = tid >> 6;       // my sequence
        const int j = tid & 63;       // my cell / enc row / loader elem

        const float* cb = cin + ((size_t)(bg * 4 + s) * T_STEPS) * KIN + j;
        float xa = 0.0f;
        float benc = 0.0f;
        if (j < ENC) benc = b_enc[j];

        hbuf[s][j] = 0.0f;            // h0 = 0
        if (j < KIN) {                // x(0..2) into the ring; LDG x(3)
            xr[s][0][j] = __ldg(cb + (size_t)TMAP(0) * KIN);
            xr[s][1][j] = __ldg(cb + (size_t)TMAP(1) * KIN);
            xr[s][2][j] = __ldg(cb + (size_t)TMAP(2) * KIN);
            xa          = __ldg(cb + (size_t)TMAP(3) * KIN);
        }
        __syncthreads();              // wesmT + xr visible

        // prologue: enc(0), enc(1)
        if (j < ENC) {
#pragma unroll
            for (int m = 0; m < 2; m++) {
                ull acc = 0ull;
                const float* xb = &xr[s][m][0];
#pragma unroll
                for (int c = 0; c < 15; c++) {
                    const ulonglong2 v = *reinterpret_cast<const ulonglong2*>(xb + 4 * c);
                    ffma2(acc, *reinterpret_cast<const ull*>(&wesmT[2 * c][j]), v.x);
                    ffma2(acc, *reinterpret_cast<const ull*>(&wesmT[2 * c + 1][j]), v.y);
                }
                float l, h;
                unpack2(acc, l, h);
                encr[s][m][j] = benc + l + h;
            }
        }
        BARRV(1 + s, 320);            // empty_s: seq s ready for t=0

        float cst = 0.0f;
        for (int t = 0; t < T_STEPS; t++) {
            BSYNC(5 + s, 320);        // full_s: partials(s,t) ready

            // epilogue: 1 cell
            {
                const float gi = gps[s][0][j]       + gps[s][1][j];
                const float gf = gps[s][0][64 + j]  + gps[s][1][64 + j];
                const float gg = gps[s][0][128 + j] + gps[s][1][128 + j];
                const float go = gps[s][0][192 + j] + gps[s][1][192 + j];

                const float ig = fast_sigmoid(gi);
                const float fg = fast_sigmoid(gf);
                const float og = fast_sigmoid(go);
                const float gt = fast_tanh(gg);
                cst = fg * cst + ig * gt;
                hbuf[s][j] = og * fast_tanh(cst);
            }
            BARRV(1 + s, 320);        // empty_s: h(s,t+1) published

            // loader: stage x(t+3), fetch x(t+4)
            if (j < KIN) {
                const int sl3 = (t + 3) % 3;
                if (t + 3 < T_STEPS) xr[s][sl3][j] = xa;
                if (t + 4 < T_STEPS) xa = __ldg(cb + (size_t)TMAP(t + 4) * KIN);
            }
            // stage1: enc(t+2) from xr[(t+2)%3]
            if (j < ENC && (t + 2) < T_STEPS) {
                const int sl2 = (t + 2) % 3;
                ull acc = 0ull;
                const float* xb = &xr[s][sl2][0];
#pragma unroll
                for (int c = 0; c < 15; c++) {
                    const ulonglong2 v = *reinterpret_cast<const ulonglong2*>(xb + 4 * c);
                    ffma2(acc, *reinterpret_cast<const ull*>(&wesmT[2 * c][j]), v.x);
                    ffma2(acc, *reinterpret_cast<const ull*>(&wesmT[2 * c + 1][j]), v.y);
                }
                float l, h;
                unpack2(acc, l, h);
                encr[s][sl2][j] = benc + l + h;
            }
        }
        g_cfin[dir][bg * 4 + s][j] = cst;
    }
}

// ---------------------------------------------------------------------------
__global__ void final_kernel(const float* __restrict__ W_fin,
                             const float* __restrict__ b_fin,
                             float* __restrict__ out) {
    const int b = threadIdx.x;
    float a0 = b_fin[0], a1 = b_fin[1], a2 = b_fin[2];
#pragma unroll
    for (int j = 0; j < HID; j++) {
        const float cf = g_cfin[0][b][j];
        a0 += W_fin[0 * 128 + j] * cf;
        a1 += W_fin[1 * 128 + j] * cf;
        a2 += W_fin[2 * 128 + j] * cf;
    }
#pragma unroll
    for (int j = 0; j < HID; j++) {
        const float cb = g_cfin[1][b][j];
        a0 += W_fin[0 * 128 + 64 + j] * cb;
        a1 += W_fin[1 * 128 + 64 + j] * cb;
        a2 += W_fin[2 * 128 + 64 + j] * cb;
    }
    out[b * 3 + 0] = a0;
    out[b * 3 + 1] = a1;
    out[b * 3 + 2] = a2;
}

extern "C" void kernel_launch(void* const* d_in, const int* in_sizes, int n_in,
                              void* d_out, int out_size) {
    (void)in_sizes; (void)n_in; (void)out_size;
    const float* c      = (const float*)d_in[0];
    const float* W_enc  = (const float*)d_in[1];
    const float* b_enc  = (const float*)d_in[2];
    const float* W_ih_f = (const float*)d_in[3];
    const float* W_hh_f = (const float*)d_in[4];
    const float* b_f    = (const float*)d_in[5];
    const float* W_ih_b = (const float*)d_in[6];
    const float* W_hh_b = (const float*)d_in[7];
    const float* b_b    = (const float*)d_in[8];
    const float* W_fin  = (const float*)d_in[9];
    const float* b_fin  = (const float*)d_in[10];
    float* out = (float*)d_out;

    // 3 pads keep ncu -s 5 -c 1 aligned on lstm_kernel
    pad_kernel<<<1, 32>>>();
    pad_kernel<<<1, 32>>>();
    pad_kernel<<<1, 32>>>();
    lstm_kernel<<<128, 512>>>(c, W_enc, b_enc,
                              W_ih_f, W_hh_f, b_f,
                              W_ih_b, W_hh_b, b_b);
    final_kernel<<<1, 256>>>(W_fin, b_fin, out);
}